// round 11
// baseline (speedup 1.0000x reference)
#include <cuda_runtime.h>
#include <cuda_bf16.h>
#include <cstdint>

// out[i,j,:] = W[d_res] + W[66+d_tok] + same_entity*W[132] + W[133+d_chain]
//
// Cross-chain (~98.4% of pairs): value is one of 10 precombined vectors
//     tab[c + 5e] = W[65]+W[131]+W[133+c] + e*W[132]
// Same-chain (~1.6%): gather W rows from L2 via __ldg.
// Per-j decision hoisted into packd[] prologue.
//
// NEW (R11): bulk async write path. Warps stage 16-j (8 KB) tiles in
// double-buffered smem, then cp.async.bulk.global.shared::cta drains each
// tile as ONE contiguous 8 KB burst (depth-2 pipeline). Tests whether the
// 5.9 TB/s plateau was an STG-path artifact. __launch_bounds__(256,8)
// forces 8 blocks/SM -> all 1024 blocks resident in a single wave.

#define TILE_J     16
#define TILE_BYTES (TILE_J * 128 * 4)   // 8192

__device__ __forceinline__ float4 f4add(float4 a, float4 b) {
    return make_float4(a.x + b.x, a.y + b.y, a.z + b.z, a.w + b.w);
}

__device__ __forceinline__ uint32_t smem_u32(const void* p) {
    return (uint32_t)__cvta_generic_to_shared(p);
}

__global__ __launch_bounds__(256, 8) void relpos_kernel(
    const float* __restrict__ feats,   // [n, 10]
    const float* __restrict__ W,       // [139, 128]
    float* __restrict__ out,           // [n, n, 128]
    int n)
{
    extern __shared__ char smem_raw[];
    float4* tab   = (float4*)smem_raw;                    // 10*32 float4 = 5120 B
    int*    packd = (int*)(smem_raw + 5120);              // n ints
    const int packd_bytes = (n * 4 + 127) & ~127;         // keep buffers 128B-aligned
    char*   bufs  = smem_raw + 5120 + packd_bytes;        // 2 * 8192 B

    const int tid = threadIdx.x;
    const int i   = blockIdx.x;

    const float* fi = feats + (size_t)i * 10;
    const int ri = (int)fi[0], ti = (int)fi[1], ai = (int)fi[2],
              ei = (int)fi[3], si = (int)fi[4];

    // ---- Prologue 1: the 10 combined cross-chain vectors -------------------
    for (int idx = tid; idx < 10 * 128; idx += blockDim.x) {
        const int r = idx >> 7;        // 0..9
        const int c = idx & 127;
        float v = __ldg(W +  65 * 128 + c)
                + __ldg(W + 131 * 128 + c)
                + __ldg(W + (133 + (r % 5)) * 128 + c);
        if (r >= 5) v += __ldg(W + 132 * 128 + c);   // same-entity variant
        ((float*)tab)[idx] = v;
    }

    // ---- Prologue 2: per-j packed decision ---------------------------------
    for (int j = tid; j < n; j += blockDim.x) {
        const float* fj = feats + (size_t)j * 10;
        const int rj = (int)__ldg(fj + 0);
        const int tj = (int)__ldg(fj + 1);
        const int aj = (int)__ldg(fj + 2);
        const int ej = (int)__ldg(fj + 3);
        const int sj = (int)__ldg(fj + 4);
        const int e  = (ei == ej) ? 1 : 0;

        int p;
        if (ai == aj) {                       // rare same-chain path
            const int dr    = ri - rj;
            const int d_res = min(max(dr + 32, 0), 64);
            const int d_tok = (dr == 0) ? min(max(ti - tj + 32, 0), 64) : 65;
            p = (int)0x80000000 | (e << 14) | (d_tok << 7) | d_res;
        } else {                              // hot path: table index 0..9
            const int d_chain = min(max(si - sj + 2, 0), 4);
            p = d_chain + 5 * e;
        }
        packd[j] = p;
    }
    __syncthreads();

    // ---- Main loop: fill 8 KB smem tiles, drain via bulk async stores ------
    const int lane = tid & 31;
    const int w    = tid >> 5;                // 8 warps, 2 j's each per tile
    const float4* Wg4 = (const float4*)W;
    float* out_row = out + (size_t)i * n * 128;

    const int ntiles = (n + TILE_J - 1) / TILE_J;

    for (int t = 0; t < ntiles; ++t) {
        const int  buf  = t & 1;
        float4*    bufp = (float4*)(bufs + buf * TILE_BYTES);
        const int  j0   = t * TILE_J;

        // Recycle buffer: ensure the bulk store issued 2 tiles ago finished
        // reading this buffer (<=1 group pending).
        if (t >= 2 && tid == 0)
            asm volatile("cp.async.bulk.wait_group 1;" ::: "memory");
        __syncthreads();

        #pragma unroll
        for (int k = 0; k < TILE_J / 8; ++k) {
            const int jl = w * (TILE_J / 8) + k;     // 0..15
            const int j  = j0 + jl;
            if (j < n) {
                const int p = packd[j];              // warp-uniform broadcast
                float4 v;
                if (p >= 0) {
                    v = tab[p * 32 + lane];          // 1 LDS.128, conflict-free
                } else {                             // rare same-chain gather
                    const int d_res = p & 127;
                    const int d_tok = (p >> 7) & 127;
                    float4 a = Wg4[d_res * 32 + lane];
                    float4 b = Wg4[(66 + d_tok) * 32 + lane];
                    float4 c = Wg4[138 * 32 + lane];
                    v = f4add(f4add(a, b), c);
                    if ((p >> 14) & 1) v = f4add(v, Wg4[132 * 32 + lane]);
                }
                bufp[jl * 32 + lane] = v;            // STS.128, conflict-free
            }
        }

        // Order generic STS before async-proxy bulk read, then issue the burst.
        asm volatile("fence.proxy.async.shared::cta;" ::: "memory");
        __syncthreads();
        if (tid == 0) {
            const int nj = min(TILE_J, n - j0);
            asm volatile(
                "cp.async.bulk.global.shared::cta.bulk_group [%0], [%1], %2;"
                :: "l"(out_row + (size_t)j0 * 128),
                   "r"(smem_u32(bufp)),
                   "r"(nj * 512)
                : "memory");
            asm volatile("cp.async.bulk.commit_group;" ::: "memory");
        }
    }

    // All bulk writes must land before the kernel completes.
    if (tid == 0)
        asm volatile("cp.async.bulk.wait_group 0;" ::: "memory");
    __syncthreads();
}

extern "C" void kernel_launch(void* const* d_in, const int* in_sizes, int n_in,
                              void* d_out, int out_size)
{
    const float* feats = (const float*)d_in[0];   // [1, n, 10] float32
    const float* W     = (const float*)d_in[1];   // [139, 128] float32
    float* out         = (float*)d_out;           // [1, n, n, 128] float32

    const int n = in_sizes[0] / 10;               // b = 1
    const size_t packd_bytes = ((size_t)n * 4 + 127) & ~(size_t)127;
    const size_t smem = 5120 + packd_bytes + 2 * TILE_BYTES;

    if (smem > 48 * 1024) {
        cudaFuncSetAttribute(relpos_kernel,
                             cudaFuncAttributeMaxDynamicSharedMemorySize,
                             (int)smem);
    }
    relpos_kernel<<<n, 256, smem>>>(feats, W, out, n);
}